// round 4
// baseline (speedup 1.0000x reference)
#include <cuda_runtime.h>
#include <cuda_bf16.h>
#include <math.h>

#define BMAX 2048
#define KD   256
#define PD   256
#define SD   10
#define SP   5     // sample pairs
#define JG   128   // column-pair groups

// per-batch partial results (allocation-free scratch)
__device__ float g_pen[BMAX];
__device__ float g_lmse[BMAX];

typedef unsigned long long u64;

__device__ __forceinline__ u64 ffma2(u64 a, u64 b, u64 c) {
    u64 d;
    asm("fma.rn.f32x2 %0, %1, %2, %3;" : "=l"(d) : "l"(a), "l"(b), "l"(c));
    return d;
}
__device__ __forceinline__ u64 bcast2(float p) {
    u64 d; unsigned u = __float_as_uint(p);
    asm("mov.b64 %0, {%1, %1};" : "=l"(d) : "r"(u));
    return d;
}
__device__ __forceinline__ float2 unpack2(u64 a) {
    float2 r;
    asm("mov.b64 {%0, %1}, %2;" : "=f"(r.x), "=f"(r.y) : "l"(a));
    return r;
}

__global__ __launch_bounds__(256)
void vil_main_kernel(const float* __restrict__ y_pred,
                     const float* __restrict__ y_true,
                     const float* __restrict__ Pp,
                     const float* __restrict__ params,
                     const float* __restrict__ Xs)
{
    const int b    = blockIdx.x;
    const int tid  = threadIdx.x;
    const int lane = tid & 31;
    const int w    = tid >> 5;

    __shared__ float2 xsp[SP][KD];     // masked X, sample-pair packed, 10 KB
    __shared__ float4 part[SP][JG];    // k-slice-1 partials, 10 KB
    __shared__ float  cacc[SD][PD];    // X@P results, 10 KB
    __shared__ float  hms[SD];

    const int n  = (int)params[b * 3 + 0];
    const int kb = (int)params[b * 3 + 1];
    const int mb = (int)params[b * 3 + 2];
    const int nk = n - kb;

    // ---- load X[b], masked, packed as (x[2sp][k], x[2sp+1][k]) ----
    const float* Xb = Xs + (size_t)b * SD * KD;
    for (int idx = tid; idx < SP * KD; idx += 256) {
        int sp = idx >> 8;        // / KD
        int k  = idx & (KD - 1);
        float a = Xb[(2 * sp)     * KD + k];
        float c = Xb[(2 * sp + 1) * KD + k];
        if (k >= kb) { a = 0.0f; c = 0.0f; }
        xsp[sp][k] = make_float2(a, c);
    }
    __syncthreads();

    // ---- GEMM: k-split 2-way, column-pair per thread ----
    // thread (ks, jg): k in [128*ks, 128*ks+128), cols {2jg, 2jg+1}
    const int jg = tid & (JG - 1);
    const int ks = tid >> 7;
    const int k0 = ks << 7;

    u64 acc[SP][2];
#pragma unroll
    for (int sp = 0; sp < SP; sp++) { acc[sp][0] = 0ull; acc[sp][1] = 0ull; }

    const float* Pb = Pp + (size_t)b * KD * PD + (size_t)k0 * PD + 2 * jg;

    float2 pc[4], pn[4];
#pragma unroll
    for (int i = 0; i < 4; i++) pc[i] = __ldcs((const float2*)(Pb + i * PD));

    for (int kk = 0; kk < 128; kk += 4) {
        if (kk + 4 < 128) {
#pragma unroll
            for (int i = 0; i < 4; i++)
                pn[i] = __ldcs((const float2*)(Pb + (kk + 4 + i) * PD));
        }
#pragma unroll
        for (int u = 0; u < 4; u += 2) {
            u64 b00 = bcast2(pc[u].x);       // P[k][2jg]   dup
            u64 b01 = bcast2(pc[u].y);       // P[k][2jg+1] dup
            u64 b10 = bcast2(pc[u + 1].x);   // P[k+1][2jg]
            u64 b11 = bcast2(pc[u + 1].y);   // P[k+1][2jg+1]
#pragma unroll
            for (int sp = 0; sp < SP; sp++) {
                // one LDS.128: x sample-pairs for k and k+1 (broadcast, conflict-free)
                const ulonglong2 xq = *(const ulonglong2*)&xsp[sp][k0 + kk + u];
                acc[sp][0] = ffma2(xq.x, b00, acc[sp][0]);
                acc[sp][1] = ffma2(xq.x, b01, acc[sp][1]);
                acc[sp][0] = ffma2(xq.y, b10, acc[sp][0]);
                acc[sp][1] = ffma2(xq.y, b11, acc[sp][1]);
            }
        }
#pragma unroll
        for (int i = 0; i < 4; i++) pc[i] = pn[i];
    }

    // ---- merge k-slices, write results to cacc ----
    if (ks == 1) {
#pragma unroll
        for (int sp = 0; sp < SP; sp++) {
            float2 a0 = unpack2(acc[sp][0]);
            float2 a1 = unpack2(acc[sp][1]);
            part[sp][jg] = make_float4(a0.x, a0.y, a1.x, a1.y);
        }
    }
    __syncthreads();
    if (ks == 0) {
#pragma unroll
        for (int sp = 0; sp < SP; sp++) {
            float4 p  = part[sp][jg];
            float2 a0 = unpack2(acc[sp][0]);
            float2 a1 = unpack2(acc[sp][1]);
            a0.x += p.x; a0.y += p.y; a1.x += p.z; a1.y += p.w;
            // sample rows 2sp, 2sp+1; columns 2jg, 2jg+1
            *(float2*)&cacc[2 * sp][2 * jg]     = make_float2(a0.x, a1.x);
            *(float2*)&cacc[2 * sp + 1][2 * jg] = make_float2(a0.y, a1.y);
        }
    }
    __syncthreads();

    // ---- per-sample top-(m+1) via iterative max extraction (1 warp / sample) ----
    for (int s = w; s < SD; s += 8) {
        float v[16];
#pragma unroll
        for (int i = 0; i < 8; i++) {
            int idx = lane + 32 * i;
            float2 xv = xsp[s >> 1][idx];
            float x = (s & 1) ? xv.y : xv.x;
            v[i] = (idx < kb) ? fabsf(x) : -1.0f;
        }
#pragma unroll
        for (int i = 0; i < 8; i++) {
            int j = lane + 32 * i;
            v[8 + i] = (j < nk) ? fabsf(cacc[s][j]) : -1.0f;
        }

        float cmax = 0.0f, cm = 0.0f;
        for (int pass = 0;; pass++) {
            float lm = v[0];
#pragma unroll
            for (int i = 1; i < 16; i++) lm = fmaxf(lm, v[i]);
            float wm = lm;
#pragma unroll
            for (int off = 16; off; off >>= 1)
                wm = fmaxf(wm, __shfl_xor_sync(0xffffffffu, wm, off));
            if (pass == 0)  cmax = wm;
            if (pass == mb) { cm = wm; break; }
            // remove exactly ONE instance of wm (matches sort semantics on ties)
            unsigned bal = __ballot_sync(0xffffffffu, lm == wm);
            int src = __ffs(bal) - 1;
            if (lane == src) {
                bool done = false;
#pragma unroll
                for (int i = 0; i < 16; i++) {
                    if (!done && v[i] == wm) { v[i] = -3.0e38f; done = true; }
                }
            }
        }
        if (lane == 0) hms[s] = cmax / (cm + 1e-9f);
    }
    __syncthreads();

    if (tid == 0) {
        float mh = hms[0];
#pragma unroll
        for (int s = 1; s < SD; s++) mh = fmaxf(mh, hms[s]);
        float yp = y_pred[b];
        float pen = ((mb + 1) <= n) ? fmaxf(mh - yp, 0.0f) : 0.0f;
        g_pen[b] = pen;
        float lp = log2f(fmaxf(yp, 1e-9f));
        float lt = log2f(fmaxf(y_true[b], 1e-9f));
        float d  = lt - lp;
        g_lmse[b] = d * d;
    }
}

__global__ __launch_bounds__(256)
void vil_finalize_kernel(float* __restrict__ out, int out_size, int Bn)
{
    __shared__ float sp[256], sl[256];
    int t = threadIdx.x;
    float p = 0.0f, l = 0.0f;
    for (int i = t; i < Bn; i += 256) { p += g_pen[i]; l += g_lmse[i]; }
    sp[t] = p; sl[t] = l;
    __syncthreads();
    for (int o = 128; o; o >>= 1) {
        if (t < o) { sp[t] += sp[t + o]; sl[t] += sl[t + o]; }
        __syncthreads();
    }
    if (t == 0) {
        float lmse = sl[0] / (float)Bn;
        float viol = sp[0] / (float)Bn;
        float tot  = lmse + 0.5f * viol;
        if (out_size > 0) out[0] = tot;
        if (out_size > 1) out[1] = lmse;
        if (out_size > 2) out[2] = viol;
    }
}

extern "C" void kernel_launch(void* const* d_in, const int* in_sizes, int n_in,
                              void* d_out, int out_size)
{
    const float* y_pred = (const float*)d_in[0];
    const float* y_true = (const float*)d_in[1];
    const float* Pp     = (const float*)d_in[2];
    const float* params = (const float*)d_in[3];
    const float* Xs     = (const float*)d_in[4];
    float* out = (float*)d_out;

    int Bn = in_sizes[0];
    if (Bn > BMAX) Bn = BMAX;

    vil_main_kernel<<<Bn, 256>>>(y_pred, y_true, Pp, params, Xs);
    vil_finalize_kernel<<<1, 256>>>(out, out_size, Bn);
}

// round 6
// speedup vs baseline: 1.0967x; 1.0967x over previous
#include <cuda_runtime.h>
#include <cuda_bf16.h>
#include <math.h>

#define BMAX 2048
#define KD   256
#define PD   256
#define SD   10
#define SP   5     // sample pairs

// per-batch partial results (allocation-free scratch)
__device__ float g_pen[BMAX];
__device__ float g_lmse[BMAX];

typedef unsigned long long u64;

__device__ __forceinline__ u64 ffma2(u64 a, u64 b, u64 c) {
    u64 d;
    asm("fma.rn.f32x2 %0, %1, %2, %3;" : "=l"(d) : "l"(a), "l"(b), "l"(c));
    return d;
}
__device__ __forceinline__ u64 bcast2(float p) {
    u64 d; unsigned u = __float_as_uint(p);
    asm("mov.b64 %0, {%1, %1};" : "=l"(d) : "r"(u));
    return d;
}

__global__ __launch_bounds__(256)
void vil_main_kernel(const float* __restrict__ y_pred,
                     const float* __restrict__ y_true,
                     const float* __restrict__ Pp,
                     const float* __restrict__ params,
                     const float* __restrict__ Xs)
{
    const int b    = blockIdx.x;
    const int tid  = threadIdx.x;
    const int lane = tid & 31;
    const int w    = tid >> 5;

    __shared__ float2 xsp[SP][KD];    // masked X, sample-pair packed, 10 KB
    __shared__ float  cacc[SD][PD];   // X@P results, 10 KB
    __shared__ float  hms[SD];

    const int n  = (int)params[b * 3 + 0];
    const int kb = (int)params[b * 3 + 1];
    const int mb = (int)params[b * 3 + 2];
    const int nk = n - kb;

    // ---- load X[b], masked, packed as (x[2sp][k], x[2sp+1][k]) ----
    const float* Xb = Xs + (size_t)b * SD * KD;
    for (int idx = tid; idx < SP * KD; idx += 256) {
        int sp = idx >> 8;        // / KD
        int k  = idx & (KD - 1);
        float a = Xb[(2 * sp)     * KD + k];
        float c = Xb[(2 * sp + 1) * KD + k];
        if (k >= kb) { a = 0.0f; c = 0.0f; }
        xsp[sp][k] = make_float2(a, c);
    }
    __syncthreads();

    // ---- GEMM: C[s, j=tid] = sum_k x[s][k] * P[b,k,j], f32x2 over sample pairs ----
    // P stream software-pipelined to distance 2 via a 4-stage register ring.
    u64 acc[SP];
#pragma unroll
    for (int sp = 0; sp < SP; sp++) acc[sp] = 0ull;

    const float* Pb = Pp + (size_t)b * KD * PD + tid;

    float buf[4][8];
#pragma unroll
    for (int i = 0; i < 8; i++) buf[0][i] = __ldcs(Pb + i * PD);
#pragma unroll
    for (int i = 0; i < 8; i++) buf[1][i] = __ldcs(Pb + (8 + i) * PD);

#pragma unroll 4
    for (int it = 0; it < KD / 8; it++) {
        const int stage  = it & 3;            // static after unroll-4
        const int lstage = (it + 2) & 3;
        if (it + 2 < KD / 8) {
#pragma unroll
            for (int i = 0; i < 8; i++)
                buf[lstage][i] = __ldcs(Pb + ((it + 2) * 8 + i) * PD);
        }
        const int k8 = it * 8;
#pragma unroll
        for (int u = 0; u < 8; u += 2) {
            u64 p0 = bcast2(buf[stage][u]);
            u64 p1 = bcast2(buf[stage][u + 1]);
#pragma unroll
            for (int sp = 0; sp < SP; sp++) {
                // one LDS.128: x sample-pairs for k8+u, k8+u+1 (broadcast, conflict-free)
                const ulonglong2 xq = *(const ulonglong2*)&xsp[sp][k8 + u];
                acc[sp] = ffma2(xq.x, p0, acc[sp]);
                acc[sp] = ffma2(xq.y, p1, acc[sp]);
            }
        }
    }

    // ---- unpack results to smem ----
#pragma unroll
    for (int sp = 0; sp < SP; sp++) {
        float2 v = *(float2*)&acc[sp];
        cacc[2 * sp][tid]     = v.x;
        cacc[2 * sp + 1][tid] = v.y;
    }
    __syncthreads();

    // ---- per-sample top-(m+1) via iterative max extraction (1 warp / sample) ----
    for (int s = w; s < SD; s += 8) {
        float v[16];
#pragma unroll
        for (int i = 0; i < 8; i++) {
            int idx = lane + 32 * i;
            float2 xv = xsp[s >> 1][idx];
            float x = (s & 1) ? xv.y : xv.x;
            v[i] = (idx < kb) ? fabsf(x) : -1.0f;
        }
#pragma unroll
        for (int i = 0; i < 8; i++) {
            int j = lane + 32 * i;
            v[8 + i] = (j < nk) ? fabsf(cacc[s][j]) : -1.0f;
        }

        float cmax = 0.0f, cm = 0.0f;
        for (int pass = 0;; pass++) {
            float lm = v[0];
#pragma unroll
            for (int i = 1; i < 16; i++) lm = fmaxf(lm, v[i]);
            float wm = lm;
#pragma unroll
            for (int off = 16; off; off >>= 1)
                wm = fmaxf(wm, __shfl_xor_sync(0xffffffffu, wm, off));
            if (pass == 0)  cmax = wm;
            if (pass == mb) { cm = wm; break; }
            // remove exactly ONE instance of wm (matches sort semantics on ties)
            unsigned bal = __ballot_sync(0xffffffffu, lm == wm);
            int src = __ffs(bal) - 1;
            if (lane == src) {
                bool done = false;
#pragma unroll
                for (int i = 0; i < 16; i++) {
                    if (!done && v[i] == wm) { v[i] = -3.0e38f; done = true; }
                }
            }
        }
        if (lane == 0) hms[s] = cmax / (cm + 1e-9f);
    }
    __syncthreads();

    if (tid == 0) {
        float mh = hms[0];
#pragma unroll
        for (int s = 1; s < SD; s++) mh = fmaxf(mh, hms[s]);
        float yp = y_pred[b];
        float pen = ((mb + 1) <= n) ? fmaxf(mh - yp, 0.0f) : 0.0f;
        g_pen[b] = pen;
        float lp = log2f(fmaxf(yp, 1e-9f));
        float lt = log2f(fmaxf(y_true[b], 1e-9f));
        float d  = lt - lp;
        g_lmse[b] = d * d;
    }
}

__global__ __launch_bounds__(256)
void vil_finalize_kernel(float* __restrict__ out, int out_size, int Bn)
{
    __shared__ float sp[256], sl[256];
    int t = threadIdx.x;
    float p = 0.0f, l = 0.0f;
    for (int i = t; i < Bn; i += 256) { p += g_pen[i]; l += g_lmse[i]; }
    sp[t] = p; sl[t] = l;
    __syncthreads();
    for (int o = 128; o; o >>= 1) {
        if (t < o) { sp[t] += sp[t + o]; sl[t] += sl[t + o]; }
        __syncthreads();
    }
    if (t == 0) {
        float lmse = sl[0] / (float)Bn;
        float viol = sp[0] / (float)Bn;
        float tot  = lmse + 0.5f * viol;
        if (out_size > 0) out[0] = tot;
        if (out_size > 1) out[1] = lmse;
        if (out_size > 2) out[2] = viol;
    }
}

extern "C" void kernel_launch(void* const* d_in, const int* in_sizes, int n_in,
                              void* d_out, int out_size)
{
    const float* y_pred = (const float*)d_in[0];
    const float* y_true = (const float*)d_in[1];
    const float* Pp     = (const float*)d_in[2];
    const float* params = (const float*)d_in[3];
    const float* Xs     = (const float*)d_in[4];
    float* out = (float*)d_out;

    int Bn = in_sizes[0];
    if (Bn > BMAX) Bn = BMAX;

    vil_main_kernel<<<Bn, 256>>>(y_pred, y_true, Pp, params, Xs);
    vil_finalize_kernel<<<1, 256>>>(out, out_size, Bn);
}

// round 7
// speedup vs baseline: 1.2172x; 1.1099x over previous
#include <cuda_runtime.h>
#include <cuda_bf16.h>
#include <math.h>

#define BMAX 2048
#define KD   256
#define PD   256
#define SD   10
#define SP   5              // sample pairs
#define SROWS 8             // k-rows per pipeline stage
#define NIT  (KD / SROWS)   // 32 stages
#define STAGE_BYTES (SROWS * PD * 4)   // 8192

// per-batch partial results (allocation-free scratch)
__device__ float g_pen[BMAX];
__device__ float g_lmse[BMAX];

typedef unsigned long long u64;

__device__ __forceinline__ u64 ffma2(u64 a, u64 b, u64 c) {
    u64 d;
    asm("fma.rn.f32x2 %0, %1, %2, %3;" : "=l"(d) : "l"(a), "l"(b), "l"(c));
    return d;
}
__device__ __forceinline__ u64 bcast2(float p) {
    u64 d; unsigned u = __float_as_uint(p);
    asm("mov.b64 %0, {%1, %1};" : "=l"(d) : "r"(u));
    return d;
}
__device__ __forceinline__ void cpa16(unsigned saddr, const float* g) {
    asm volatile("cp.async.cg.shared.global [%0], [%1], 16;" :: "r"(saddr), "l"(g));
}
__device__ __forceinline__ void cpa_commit() {
    asm volatile("cp.async.commit_group;");
}

__global__ __launch_bounds__(256, 4)
void vil_main_kernel(const float* __restrict__ y_pred,
                     const float* __restrict__ y_true,
                     const float* __restrict__ Pp,
                     const float* __restrict__ params,
                     const float* __restrict__ Xs)
{
    const int b    = blockIdx.x;
    const int tid  = threadIdx.x;
    const int lane = tid & 31;
    const int w    = tid >> 5;

    __shared__ float2 xsp[SP][KD];                       // masked X, 10 KB
    __shared__ __align__(16) float pool[4 * SROWS * PD]; // 32 KB: P stages, later cacc
    __shared__ float hms[SD];

    float (*pst)[SROWS][PD] = (float (*)[SROWS][PD])pool; // [stage][row][col]
    float (*cacc)[PD]       = (float (*)[PD])pool;        // [SD][PD] alias (post-GEMM)

    const int n  = (int)params[b * 3 + 0];
    const int kb = (int)params[b * 3 + 1];
    const int mb = (int)params[b * 3 + 2];
    const int nk = n - kb;

    const float*   Pbase     = Pp + (size_t)b * KD * PD;
    const unsigned pool_base = (unsigned)__cvta_generic_to_shared(pool);

    // ---- load X[b], masked, packed as (x[2sp][k], x[2sp+1][k]) ----
    const float* Xb = Xs + (size_t)b * SD * KD;
    for (int idx = tid; idx < SP * KD; idx += 256) {
        int s = idx >> 8;
        int k = idx & (KD - 1);
        float a = Xb[(2 * s)     * KD + k];
        float c = Xb[(2 * s + 1) * KD + k];
        if (k >= kb) { a = 0.0f; c = 0.0f; }
        xsp[s][k] = make_float2(a, c);
    }

    // ---- prologue: issue stages 0..2 (each stage = contiguous 8 KB of P) ----
#pragma unroll
    for (int it = 0; it < 3; it++) {
        unsigned dst = pool_base + (it & 3) * STAGE_BYTES;
        const float* src = Pbase + it * SROWS * PD;
        cpa16(dst + tid * 16,        src + tid * 4);
        cpa16(dst + 4096 + tid * 16, src + 1024 + tid * 4);
        cpa_commit();
    }

    u64 acc[SP];
#pragma unroll
    for (int s = 0; s < SP; s++) acc[s] = 0ull;

    // ---- pipelined GEMM mainloop ----
    for (int it = 0; it < NIT; it++) {
        // wait until stage `it` is resident (groups allowed to stay pending: 2/1/0)
        if (it <= NIT - 3)      asm volatile("cp.async.wait_group 2;");
        else if (it == NIT - 2) asm volatile("cp.async.wait_group 1;");
        else                    asm volatile("cp.async.wait_group 0;");
        __syncthreads();   // publish stage `it`; also fences reads of stage it-1

        const int st = it & 3;
        const int k8 = it * SROWS;
#pragma unroll
        for (int u = 0; u < SROWS; u += 2) {
            u64 p0 = bcast2(pst[st][u][tid]);
            u64 p1 = bcast2(pst[st][u + 1][tid]);
#pragma unroll
            for (int s = 0; s < SP; s++) {
                // one LDS.128: x sample-pairs for k8+u, k8+u+1 (broadcast, conflict-free)
                const ulonglong2 xq = *(const ulonglong2*)&xsp[s][k8 + u];
                acc[s] = ffma2(xq.x, p0, acc[s]);
                acc[s] = ffma2(xq.y, p1, acc[s]);
            }
        }

        // issue stage it+3 (overwrites ring slot (it-1)&3, drained by the barrier above)
        if (it + 3 < NIT) {
            unsigned dst = pool_base + ((it + 3) & 3) * STAGE_BYTES;
            const float* src = Pbase + (it + 3) * SROWS * PD;
            cpa16(dst + tid * 16,        src + tid * 4);
            cpa16(dst + 4096 + tid * 16, src + 1024 + tid * 4);
            cpa_commit();
        }
    }

    // ---- unpack results into cacc (aliases stages 0/1 region; safe: last reads hit stage 3) ----
#pragma unroll
    for (int s = 0; s < SP; s++) {
        float2 v = *(float2*)&acc[s];
        cacc[2 * s][tid]     = v.x;
        cacc[2 * s + 1][tid] = v.y;
    }
    __syncthreads();

    // ---- per-sample top-(m+1) via iterative max extraction (1 warp / sample) ----
    for (int s = w; s < SD; s += 8) {
        float v[16];
#pragma unroll
        for (int i = 0; i < 8; i++) {
            int idx = lane + 32 * i;
            float2 xv = xsp[s >> 1][idx];
            float x = (s & 1) ? xv.y : xv.x;
            v[i] = (idx < kb) ? fabsf(x) : -1.0f;
        }
#pragma unroll
        for (int i = 0; i < 8; i++) {
            int j = lane + 32 * i;
            v[8 + i] = (j < nk) ? fabsf(cacc[s][j]) : -1.0f;
        }

        float cmax = 0.0f, cm = 0.0f;
        for (int pass = 0;; pass++) {
            float lm = v[0];
#pragma unroll
            for (int i = 1; i < 16; i++) lm = fmaxf(lm, v[i]);
            float wm = lm;
#pragma unroll
            for (int off = 16; off; off >>= 1)
                wm = fmaxf(wm, __shfl_xor_sync(0xffffffffu, wm, off));
            if (pass == 0)  cmax = wm;
            if (pass == mb) { cm = wm; break; }
            // remove exactly ONE instance of wm (matches sort semantics on ties)
            unsigned bal = __ballot_sync(0xffffffffu, lm == wm);
            int src = __ffs(bal) - 1;
            if (lane == src) {
                bool done = false;
#pragma unroll
                for (int i = 0; i < 16; i++) {
                    if (!done && v[i] == wm) { v[i] = -3.0e38f; done = true; }
                }
            }
        }
        if (lane == 0) hms[s] = cmax / (cm + 1e-9f);
    }
    __syncthreads();

    if (tid == 0) {
        float mh = hms[0];
#pragma unroll
        for (int s = 1; s < SD; s++) mh = fmaxf(mh, hms[s]);
        float yp = y_pred[b];
        float pen = ((mb + 1) <= n) ? fmaxf(mh - yp, 0.0f) : 0.0f;
        g_pen[b] = pen;
        float lp = log2f(fmaxf(yp, 1e-9f));
        float lt = log2f(fmaxf(y_true[b], 1e-9f));
        float d  = lt - lp;
        g_lmse[b] = d * d;
    }
}

__global__ __launch_bounds__(256)
void vil_finalize_kernel(float* __restrict__ out, int out_size, int Bn)
{
    __shared__ float sp[256], sl[256];
    int t = threadIdx.x;
    float p = 0.0f, l = 0.0f;
    for (int i = t; i < Bn; i += 256) { p += g_pen[i]; l += g_lmse[i]; }
    sp[t] = p; sl[t] = l;
    __syncthreads();
    for (int o = 128; o; o >>= 1) {
        if (t < o) { sp[t] += sp[t + o]; sl[t] += sl[t + o]; }
        __syncthreads();
    }
    if (t == 0) {
        float lmse = sl[0] / (float)Bn;
        float viol = sp[0] / (float)Bn;
        float tot  = lmse + 0.5f * viol;
        if (out_size > 0) out[0] = tot;
        if (out_size > 1) out[1] = lmse;
        if (out_size > 2) out[2] = viol;
    }
}

extern "C" void kernel_launch(void* const* d_in, const int* in_sizes, int n_in,
                              void* d_out, int out_size)
{
    const float* y_pred = (const float*)d_in[0];
    const float* y_true = (const float*)d_in[1];
    const float* Pp     = (const float*)d_in[2];
    const float* params = (const float*)d_in[3];
    const float* Xs     = (const float*)d_in[4];
    float* out = (float*)d_out;

    int Bn = in_sizes[0];
    if (Bn > BMAX) Bn = BMAX;

    vil_main_kernel<<<Bn, 256>>>(y_pred, y_true, Pp, params, Xs);
    vil_finalize_kernel<<<1, 256>>>(out, out_size, Bn);
}